// round 2
// baseline (speedup 1.0000x reference)
#include <cuda_runtime.h>

// Problem constants
// B=4, S=4096, H=4096, D=1024
#define BATCH 4
#define SEQ   4096
#define HID   4096
#define DHEAD 1024

// Scratch (device globals: allocation-free per harness rules)
__device__ float g_qkv [ (size_t)BATCH * SEQ * 3 * DHEAD ]; // 201 MB
__device__ float g_attn[ (size_t)BATCH * SEQ * SEQ        ]; // 268 MB
__device__ float g_out [ (size_t)BATCH * SEQ * DHEAD      ]; //  67 MB

#define BM 128
#define BN 128
#define BK 8
#define TM 8
#define TN 8

// Classic SIMT sgemm: C[M,N] = alpha * A * op(B) (+ bias), row-major, strided batch.
// TRANSB=false: B is [K,N] (ldb = row stride). TRANSB=true: B is [N,K], C = A*B^T.
template <bool TRANSB>
__global__ __launch_bounds__(256) void sgemm_kernel(
    const float* __restrict__ A, int lda, long long sA,
    const float* __restrict__ B, int ldb, long long sB,
    const float* __restrict__ bias,
    float* __restrict__ C, int ldc, long long sC,
    int K, float alpha)
{
    __shared__ float As[BK][BM];
    __shared__ float Bs[BK][BN];

    const int tid = threadIdx.x;
    const int bx = blockIdx.x, by = blockIdx.y, bz = blockIdx.z;

    A += (long long)bz * sA + (size_t)by * BM * lda;
    if (TRANSB) B += (long long)bz * sB + (size_t)bx * BN * ldb;
    else        B += (long long)bz * sB + bx * BN;
    C += (long long)bz * sC + (size_t)by * BM * ldc + bx * BN;

    // A-tile loader: 128 rows x 8 k, one float4 along K per thread
    const int lrow = tid >> 1;       // 0..127
    const int lk   = (tid & 1) * 4;  // 0 or 4
    // B-tile loader (NN): 8 rows x 128 cols
    const int brow = tid >> 5;       // 0..7
    const int bcol = (tid & 31) * 4; // 0..124

    const int tx = tid & 15;   // N direction
    const int ty = tid >> 4;   // M direction

    float acc[TM][TN];
    #pragma unroll
    for (int i = 0; i < TM; i++)
        #pragma unroll
        for (int j = 0; j < TN; j++) acc[i][j] = 0.f;

    for (int k0 = 0; k0 < K; k0 += BK) {
        float4 av = *reinterpret_cast<const float4*>(&A[(size_t)lrow * lda + k0 + lk]);
        As[lk + 0][lrow] = av.x;
        As[lk + 1][lrow] = av.y;
        As[lk + 2][lrow] = av.z;
        As[lk + 3][lrow] = av.w;
        if (TRANSB) {
            float4 bv = *reinterpret_cast<const float4*>(&B[(size_t)lrow * ldb + k0 + lk]);
            Bs[lk + 0][lrow] = bv.x;
            Bs[lk + 1][lrow] = bv.y;
            Bs[lk + 2][lrow] = bv.z;
            Bs[lk + 3][lrow] = bv.w;
        } else {
            float4 bv = *reinterpret_cast<const float4*>(&B[(size_t)(k0 + brow) * ldb + bcol]);
            *reinterpret_cast<float4*>(&Bs[brow][bcol]) = bv;
        }
        __syncthreads();
        #pragma unroll
        for (int kk = 0; kk < BK; kk++) {
            float a[TM], b[TN];
            #pragma unroll
            for (int h = 0; h < 2; h++) {
                float4 t = *reinterpret_cast<const float4*>(&As[kk][ty * TM + h * 4]);
                a[h * 4 + 0] = t.x; a[h * 4 + 1] = t.y;
                a[h * 4 + 2] = t.z; a[h * 4 + 3] = t.w;
            }
            #pragma unroll
            for (int h = 0; h < 2; h++) {
                float4 t = *reinterpret_cast<const float4*>(&Bs[kk][tx * TN + h * 4]);
                b[h * 4 + 0] = t.x; b[h * 4 + 1] = t.y;
                b[h * 4 + 2] = t.z; b[h * 4 + 3] = t.w;
            }
            #pragma unroll
            for (int i = 0; i < TM; i++)
                #pragma unroll
                for (int j = 0; j < TN; j++)
                    acc[i][j] += a[i] * b[j];
        }
        __syncthreads();
    }

    #pragma unroll
    for (int i = 0; i < TM; i++) {
        const int r = ty * TM + i;
        #pragma unroll
        for (int j = 0; j < TN; j += 4) {
            const int c = tx * TN + j;
            float4 v;
            v.x = acc[i][j + 0] * alpha;
            v.y = acc[i][j + 1] * alpha;
            v.z = acc[i][j + 2] * alpha;
            v.w = acc[i][j + 3] * alpha;
            if (bias) {
                v.x += bias[bx * BN + c + 0];
                v.y += bias[bx * BN + c + 1];
                v.z += bias[bx * BN + c + 2];
                v.w += bias[bx * BN + c + 3];
            }
            *reinterpret_cast<float4*>(&C[(size_t)r * ldc + c]) = v;
        }
    }
}

// In-place row softmax over 4096 columns; one block (256 thr) per row.
__global__ __launch_bounds__(256) void softmax_kernel(float* __restrict__ P)
{
    const size_t row = blockIdx.x;
    float* p = P + row * (size_t)SEQ;
    const int tid = threadIdx.x;

    float v[16];
    float mx = -1e30f;
    #pragma unroll
    for (int i = 0; i < 16; i++) {
        v[i] = p[i * 256 + tid];
        mx = fmaxf(mx, v[i]);
    }

    __shared__ float red[8];
    #pragma unroll
    for (int off = 16; off; off >>= 1)
        mx = fmaxf(mx, __shfl_xor_sync(0xFFFFFFFFu, mx, off));
    if ((tid & 31) == 0) red[tid >> 5] = mx;
    __syncthreads();
    mx = red[0];
    #pragma unroll
    for (int w = 1; w < 8; w++) mx = fmaxf(mx, red[w]);

    float sum = 0.f;
    #pragma unroll
    for (int i = 0; i < 16; i++) {
        v[i] = __expf(v[i] - mx);
        sum += v[i];
    }
    __syncthreads();  // red reuse
    #pragma unroll
    for (int off = 16; off; off >>= 1)
        sum += __shfl_xor_sync(0xFFFFFFFFu, sum, off);
    if ((tid & 31) == 0) red[tid >> 5] = sum;
    __syncthreads();
    sum = 0.f;
    #pragma unroll
    for (int w = 0; w < 8; w++) sum += red[w];

    const float inv = 1.f / sum;
    #pragma unroll
    for (int i = 0; i < 16; i++)
        p[i * 256 + tid] = v[i] * inv;
}

extern "C" void kernel_launch(void* const* d_in, const int* in_sizes, int n_in,
                              void* d_out, int out_size)
{
    const float* x    = (const float*)d_in[0];
    const float* Wqkv = (const float*)d_in[1];
    const float* bqkv = (const float*)d_in[2];
    const float* Wo   = (const float*)d_in[3];
    const float* bo   = (const float*)d_in[4];
    float* out = (float*)d_out;

    float *qkv, *attn, *aout;
    cudaGetSymbolAddress((void**)&qkv,  g_qkv);
    cudaGetSymbolAddress((void**)&attn, g_attn);
    cudaGetSymbolAddress((void**)&aout, g_out);

    const int BS = BATCH * SEQ;                       // 16384
    const long long sQKV  = (long long)SEQ * 3 * DHEAD;
    const long long sATT  = (long long)SEQ * SEQ;
    const long long sOUT  = (long long)SEQ * DHEAD;
    const float scale = 0.03125f;                     // 1/sqrt(1024)

    dim3 blk(256);

    // 1. qkv = x @ Wqkv + bqkv   [16384 x 3072, K=4096]
    sgemm_kernel<false><<<dim3((3 * DHEAD) / BN, BS / BM, 1), blk>>>(
        x, HID, 0, Wqkv, 3 * DHEAD, 0, bqkv, qkv, 3 * DHEAD, 0, HID, 1.f);

    // 2. scores = scale * Q @ K^T  (batched, 4 x [4096 x 4096, K=1024])
    sgemm_kernel<true><<<dim3(SEQ / BN, SEQ / BM, BATCH), blk>>>(
        qkv, 3 * DHEAD, sQKV, qkv + DHEAD, 3 * DHEAD, sQKV, nullptr,
        attn, SEQ, sATT, DHEAD, scale);

    // 3. softmax rows
    softmax_kernel<<<BS, 256>>>(attn);

    // 4. out = P @ V  (batched, 4 x [4096 x 1024, K=4096])
    sgemm_kernel<false><<<dim3(DHEAD / BN, SEQ / BM, BATCH), blk>>>(
        attn, SEQ, sATT, qkv + 2 * DHEAD, 3 * DHEAD, sQKV, nullptr,
        aout, DHEAD, sOUT, SEQ, 1.f);

    // 5. y = out @ Wo + bo   [16384 x 4096, K=1024]
    sgemm_kernel<false><<<dim3(HID / BN, BS / BM, 1), blk>>>(
        aout, DHEAD, 0, Wo, HID, 0, bo, out, HID, 0, DHEAD, 1.f);
}

// round 4
// speedup vs baseline: 3.1241x; 3.1241x over previous
#include <cuda_runtime.h>
#include <cstdint>

// B=4, S=4096, H=4096, D=1024
#define BATCH 4
#define SEQ   4096
#define HID   4096
#define DHEAD 1024

// Scratch (device globals: allocation-free per harness rules)
__device__ float g_qkv [ (size_t)BATCH * SEQ * 3 * DHEAD ]; // 201 MB
__device__ float g_attn[ (size_t)BATCH * SEQ * SEQ        ]; // 268 MB
__device__ float g_out [ (size_t)BATCH * SEQ * DHEAD      ]; //  67 MB

#define BM 128
#define BN 128
#define BK 16
#define ASTRIDE (BK + 4)     // 20 floats: bank = (20g+tg)%32 -> conflict-free
#define BSTRIDE (BN + 8)     // 136 floats: bank = (8tg+g)%32 -> conflict-free

__device__ __forceinline__ void cp_async16(void* smem, const void* gmem) {
    uint32_t s = (uint32_t)__cvta_generic_to_shared(smem);
    asm volatile("cp.async.cg.shared.global [%0], [%1], 16;" :: "r"(s), "l"(gmem));
}
__device__ __forceinline__ void cp_commit() { asm volatile("cp.async.commit_group;"); }
__device__ __forceinline__ void cp_wait0()  { asm volatile("cp.async.wait_group 0;"); }

__device__ __forceinline__ uint32_t f2tf(float f) {
    uint32_t u;
    asm("cvt.rna.tf32.f32 %0, %1;" : "=r"(u) : "f"(f));
    return u;
}

__device__ __forceinline__ void mma_tf32(float* c, const uint32_t* a, const uint32_t* b) {
    asm volatile(
        "mma.sync.aligned.m16n8k8.row.col.f32.tf32.tf32.f32 "
        "{%0,%1,%2,%3}, {%4,%5,%6,%7}, {%8,%9}, {%0,%1,%2,%3};"
        : "+f"(c[0]), "+f"(c[1]), "+f"(c[2]), "+f"(c[3])
        : "r"(a[0]), "r"(a[1]), "r"(a[2]), "r"(a[3]), "r"(b[0]), "r"(b[1]));
}

// C[M,N] = alpha * A * op(B) (+ bias), row-major, strided batch, tf32 tensor cores.
// TRANSB=false: B is [K,N]. TRANSB=true: B is [N,K], C = A*B^T.
template <bool TRANSB>
__global__ __launch_bounds__(256) void mma_gemm(
    const float* __restrict__ A, int lda, long long sA,
    const float* __restrict__ B, int ldb, long long sB,
    const float* __restrict__ bias,
    float* __restrict__ C, int ldc, long long sC,
    int K, float alpha)
{
    __shared__ float As[2][BM][ASTRIDE];
    __shared__ float Bs[2][TRANSB ? BN : BK][TRANSB ? ASTRIDE : BSTRIDE];

    const int tid = threadIdx.x;
    const int bx = blockIdx.x, by = blockIdx.y, bz = blockIdx.z;

    A += (long long)bz * sA + (size_t)by * BM * lda;
    if (TRANSB) B += (long long)bz * sB + (size_t)bx * BN * ldb;
    else        B += (long long)bz * sB + (size_t)bx * BN;
    C += (long long)bz * sC + (size_t)by * BM * ldc + (size_t)bx * BN;
    const float* biasp = bias ? (bias + (size_t)bx * BN) : nullptr;

    // Loader indexing (256 threads, 2 x 16B chunks each per tile)
    const int ar0 = tid >> 2;        // A/TRANSB-B: rows ar0, ar0+64
    const int ak  = (tid & 3) * 4;   // k offset (floats)
    const int br0 = tid >> 5;        // NN-B: rows br0, br0+8
    const int bc  = (tid & 31) * 4;  // col offset

    auto load_tiles = [&](int buf, int k0) {
        cp_async16(&As[buf][ar0][ak],      A + (size_t)ar0        * lda + k0 + ak);
        cp_async16(&As[buf][ar0 + 64][ak], A + (size_t)(ar0 + 64) * lda + k0 + ak);
        if (TRANSB) {
            cp_async16(&Bs[buf][ar0][ak],      B + (size_t)ar0        * ldb + k0 + ak);
            cp_async16(&Bs[buf][ar0 + 64][ak], B + (size_t)(ar0 + 64) * ldb + k0 + ak);
        } else {
            cp_async16(&Bs[buf][br0][bc],     B + (size_t)(k0 + br0)     * ldb + bc);
            cp_async16(&Bs[buf][br0 + 8][bc], B + (size_t)(k0 + br0 + 8) * ldb + bc);
        }
        cp_commit();
    };

    // Warp tiling: 8 warps as 4(M) x 2(N); warp tile 32x64
    const int lane = tid & 31;
    const int wid  = tid >> 5;
    const int m0 = (wid & 3) * 32;
    const int n0 = (wid >> 2) * 64;
    const int g  = lane >> 2;   // groupID
    const int tg = lane & 3;    // thread-in-group

    float acc[2][8][4];
    #pragma unroll
    for (int mt = 0; mt < 2; mt++)
        #pragma unroll
        for (int nt = 0; nt < 8; nt++)
            #pragma unroll
            for (int i = 0; i < 4; i++) acc[mt][nt][i] = 0.f;

    const int nIter = K / BK;
    load_tiles(0, 0);

    for (int it = 0; it < nIter; ++it) {
        cp_wait0();
        __syncthreads();
        if (it + 1 < nIter) load_tiles((it + 1) & 1, (it + 1) * BK);
        const int buf = it & 1;

        #pragma unroll
        for (int ks = 0; ks < BK; ks += 8) {
            uint32_t af[2][4];
            #pragma unroll
            for (int mt = 0; mt < 2; mt++) {
                const int r = m0 + mt * 16 + g;
                af[mt][0] = f2tf(As[buf][r]    [ks + tg]);
                af[mt][1] = f2tf(As[buf][r + 8][ks + tg]);
                af[mt][2] = f2tf(As[buf][r]    [ks + tg + 4]);
                af[mt][3] = f2tf(As[buf][r + 8][ks + tg + 4]);
            }
            uint32_t bfr[8][2];
            #pragma unroll
            for (int nt = 0; nt < 8; nt++) {
                const int c = n0 + nt * 8 + g;
                if (TRANSB) {
                    bfr[nt][0] = f2tf(Bs[buf][c][ks + tg]);
                    bfr[nt][1] = f2tf(Bs[buf][c][ks + tg + 4]);
                } else {
                    bfr[nt][0] = f2tf(Bs[buf][ks + tg]    [c]);
                    bfr[nt][1] = f2tf(Bs[buf][ks + tg + 4][c]);
                }
            }
            #pragma unroll
            for (int mt = 0; mt < 2; mt++)
                #pragma unroll
                for (int nt = 0; nt < 8; nt++)
                    mma_tf32(acc[mt][nt], af[mt], bfr[nt]);
        }
        // no trailing sync: next iter's wait+syncthreads orders WAR on buffers
    }

    // Epilogue: alpha scale + optional bias, float2 stores
    #pragma unroll
    for (int mt = 0; mt < 2; mt++) {
        #pragma unroll
        for (int nt = 0; nt < 8; nt++) {
            const int r = m0 + mt * 16 + g;
            const int c = n0 + nt * 8 + 2 * tg;
            float b0 = 0.f, b1 = 0.f;
            if (biasp) { b0 = biasp[c]; b1 = biasp[c + 1]; }
            float2 v;
            v.x = acc[mt][nt][0] * alpha + b0;
            v.y = acc[mt][nt][1] * alpha + b1;
            *reinterpret_cast<float2*>(&C[(size_t)r * ldc + c]) = v;
            v.x = acc[mt][nt][2] * alpha + b0;
            v.y = acc[mt][nt][3] * alpha + b1;
            *reinterpret_cast<float2*>(&C[(size_t)(r + 8) * ldc + c]) = v;
        }
    }
}

// In-place row softmax over 4096 columns; one block (256 thr) per row.
__global__ __launch_bounds__(256) void softmax_kernel(float* __restrict__ P)
{
    const size_t row = blockIdx.x;
    float* p = P + row * (size_t)SEQ;
    const int tid = threadIdx.x;

    float v[16];
    float mx = -1e30f;
    #pragma unroll
    for (int i = 0; i < 16; i++) {
        v[i] = p[i * 256 + tid];
        mx = fmaxf(mx, v[i]);
    }

    __shared__ float red[8];
    #pragma unroll
    for (int off = 16; off; off >>= 1)
        mx = fmaxf(mx, __shfl_xor_sync(0xFFFFFFFFu, mx, off));
    if ((tid & 31) == 0) red[tid >> 5] = mx;
    __syncthreads();
    mx = red[0];
    #pragma unroll
    for (int w = 1; w < 8; w++) mx = fmaxf(mx, red[w]);

    float sum = 0.f;
    #pragma unroll
    for (int i = 0; i < 16; i++) {
        v[i] = __expf(v[i] - mx);
        sum += v[i];
    }
    __syncthreads();
    #pragma unroll
    for (int off = 16; off; off >>= 1)
        sum += __shfl_xor_sync(0xFFFFFFFFu, sum, off);
    if ((tid & 31) == 0) red[tid >> 5] = sum;
    __syncthreads();
    sum = 0.f;
    #pragma unroll
    for (int w = 0; w < 8; w++) sum += red[w];

    const float inv = 1.f / sum;
    #pragma unroll
    for (int i = 0; i < 16; i++)
        p[i * 256 + tid] = v[i] * inv;
}

extern "C" void kernel_launch(void* const* d_in, const int* in_sizes, int n_in,
                              void* d_out, int out_size)
{
    const float* x    = (const float*)d_in[0];
    const float* Wqkv = (const float*)d_in[1];
    const float* bqkv = (const float*)d_in[2];
    const float* Wo   = (const float*)d_in[3];
    const float* bo   = (const float*)d_in[4];
    float* out = (float*)d_out;

    float *qkv, *attn, *aout;
    cudaGetSymbolAddress((void**)&qkv,  g_qkv);
    cudaGetSymbolAddress((void**)&attn, g_attn);
    cudaGetSymbolAddress((void**)&aout, g_out);

    const int BS = BATCH * SEQ;                       // 16384
    const long long sQKV = (long long)SEQ * 3 * DHEAD;
    const long long sATT = (long long)SEQ * SEQ;
    const long long sOUT = (long long)SEQ * DHEAD;
    const float scale = 0.03125f;                     // 1/sqrt(1024)

    dim3 blk(256);

    // 1. qkv = x @ Wqkv + bqkv   [16384 x 3072, K=4096]
    mma_gemm<false><<<dim3((3 * DHEAD) / BN, BS / BM, 1), blk>>>(
        x, HID, 0, Wqkv, 3 * DHEAD, 0, bqkv, qkv, 3 * DHEAD, 0, HID, 1.f);

    // 2. scores = scale * Q @ K^T  (batched, 4 x [4096 x 4096, K=1024])
    mma_gemm<true><<<dim3(SEQ / BN, SEQ / BM, BATCH), blk>>>(
        qkv, 3 * DHEAD, sQKV, qkv + DHEAD, 3 * DHEAD, sQKV, nullptr,
        attn, SEQ, sATT, DHEAD, scale);

    // 3. softmax rows
    softmax_kernel<<<BS, 256>>>(attn);

    // 4. out = P @ V  (batched, 4 x [4096 x 1024, K=4096])
    mma_gemm<false><<<dim3(DHEAD / BN, SEQ / BM, BATCH), blk>>>(
        attn, SEQ, sATT, qkv + 2 * DHEAD, 3 * DHEAD, sQKV, nullptr,
        aout, DHEAD, sOUT, SEQ, 1.f);

    // 5. y = out @ Wo + bo   [16384 x 4096, K=1024]
    mma_gemm<false><<<dim3(HID / BN, BS / BM, 1), blk>>>(
        aout, DHEAD, 0, Wo, HID, 0, bo, out, HID, 0, DHEAD, 1.f);
}

// round 5
// speedup vs baseline: 3.5151x; 1.1252x over previous
#include <cuda_runtime.h>
#include <cstdint>

// B=4, S=4096, H=4096, D=1024
#define BATCH 4
#define SEQ   4096
#define HID   4096
#define DHEAD 1024

// Scratch (device globals: allocation-free per harness rules)
__device__ float g_qkv  [ (size_t)BATCH * SEQ * 3 * DHEAD ]; // 201 MB
__device__ float g_attn [ (size_t)BATCH * SEQ * SEQ       ]; // 268 MB
__device__ float g_out  [ (size_t)BATCH * SEQ * DHEAD     ]; //  67 MB
__device__ float g_xt   [ (size_t)BATCH * SEQ * HID       ]; // 268 MB (tf32-rounded x)
__device__ float g_wqkvt[ (size_t)HID * 3 * DHEAD         ]; //  48 MB (tf32-rounded Wqkv)
__device__ float g_wot  [ (size_t)DHEAD * HID             ]; //  16 MB (tf32-rounded Wo)

#define BM 128
#define BN 128
#define BK 16
#define ASTRIDE (BK + 4)     // 20 floats: bank = (20g+tg)%32 -> conflict-free
#define BSTRIDE (BN + 8)     // 136 floats: bank = (8tg+g)%32 -> conflict-free

__device__ __forceinline__ void cp_async16(void* smem, const void* gmem) {
    uint32_t s = (uint32_t)__cvta_generic_to_shared(smem);
    asm volatile("cp.async.cg.shared.global [%0], [%1], 16;" :: "r"(s), "l"(gmem));
}
__device__ __forceinline__ void cp_commit() { asm volatile("cp.async.commit_group;"); }
__device__ __forceinline__ void cp_wait0()  { asm volatile("cp.async.wait_group 0;"); }

__device__ __forceinline__ uint32_t f2tf(float f) {
    uint32_t u;
    asm("cvt.rna.tf32.f32 %0, %1;" : "=r"(u) : "f"(f));
    return u;
}
__device__ __forceinline__ float tf32r(float f) { return __uint_as_float(f2tf(f)); }

__device__ __forceinline__ void mma_tf32(float* c, const uint32_t* a, const uint32_t* b) {
    asm volatile(
        "mma.sync.aligned.m16n8k8.row.col.f32.tf32.tf32.f32 "
        "{%0,%1,%2,%3}, {%4,%5,%6,%7}, {%8,%9}, {%0,%1,%2,%3};"
        : "+f"(c[0]), "+f"(c[1]), "+f"(c[2]), "+f"(c[3])
        : "r"(a[0]), "r"(a[1]), "r"(a[2]), "r"(a[3]), "r"(b[0]), "r"(b[1]));
}

// Elementwise tf32 rounding pass (float4 grid-stride). n4 = element count / 4.
__global__ __launch_bounds__(256) void round_kernel(
    const float4* __restrict__ in, float4* __restrict__ out, size_t n4)
{
    for (size_t i = (size_t)blockIdx.x * blockDim.x + threadIdx.x; i < n4;
         i += (size_t)gridDim.x * blockDim.x) {
        float4 v = in[i];
        v.x = tf32r(v.x); v.y = tf32r(v.y); v.z = tf32r(v.z); v.w = tf32r(v.w);
        out[i] = v;
    }
}

// C[M,N] = alpha * A * op(B) (+ bias), row-major, strided batch, tf32 tensor cores.
// INPUTS MUST ALREADY BE TF32-ROUNDED (fragments are fed raw; no in-loop cvt).
// roundC != 0: round C to tf32 on store (for intermediates feeding another GEMM).
// TRANSB=false: B is [K,N]. TRANSB=true: B is [N,K], C = A*B^T.
template <bool TRANSB>
__global__ __launch_bounds__(256, 2) void mma_gemm(
    const float* __restrict__ A, int lda, long long sA,
    const float* __restrict__ B, int ldb, long long sB,
    const float* __restrict__ bias,
    float* __restrict__ C, int ldc, long long sC,
    int K, float alpha, int roundC)
{
    __shared__ float As[2][BM][ASTRIDE];
    __shared__ float Bs[2][TRANSB ? BN : BK][TRANSB ? ASTRIDE : BSTRIDE];

    const int tid = threadIdx.x;
    const int bx = blockIdx.x, by = blockIdx.y, bz = blockIdx.z;

    A += (long long)bz * sA + (size_t)by * BM * lda;
    if (TRANSB) B += (long long)bz * sB + (size_t)bx * BN * ldb;
    else        B += (long long)bz * sB + (size_t)bx * BN;
    C += (long long)bz * sC + (size_t)by * BM * ldc + (size_t)bx * BN;
    const float* biasp = bias ? (bias + (size_t)bx * BN) : nullptr;

    // Loader indexing (256 threads, 2 x 16B chunks each per tile)
    const int ar0 = tid >> 2;        // A/TRANSB-B: rows ar0, ar0+64
    const int ak  = (tid & 3) * 4;   // k offset (floats)
    const int br0 = tid >> 5;        // NN-B: rows br0, br0+8
    const int bc  = (tid & 31) * 4;  // col offset

    auto load_tiles = [&](int buf, int k0) {
        cp_async16(&As[buf][ar0][ak],      A + (size_t)ar0        * lda + k0 + ak);
        cp_async16(&As[buf][ar0 + 64][ak], A + (size_t)(ar0 + 64) * lda + k0 + ak);
        if (TRANSB) {
            cp_async16(&Bs[buf][ar0][ak],      B + (size_t)ar0        * ldb + k0 + ak);
            cp_async16(&Bs[buf][ar0 + 64][ak], B + (size_t)(ar0 + 64) * ldb + k0 + ak);
        } else {
            cp_async16(&Bs[buf][br0][bc],     B + (size_t)(k0 + br0)     * ldb + bc);
            cp_async16(&Bs[buf][br0 + 8][bc], B + (size_t)(k0 + br0 + 8) * ldb + bc);
        }
        cp_commit();
    };

    // Warp tiling: 8 warps as 4(M) x 2(N); warp tile 32x64
    const int lane = tid & 31;
    const int wid  = tid >> 5;
    const int m0 = (wid & 3) * 32;
    const int n0 = (wid >> 2) * 64;
    const int g  = lane >> 2;   // groupID
    const int tg = lane & 3;    // thread-in-group

    float acc[2][8][4];
    #pragma unroll
    for (int mt = 0; mt < 2; mt++)
        #pragma unroll
        for (int nt = 0; nt < 8; nt++)
            #pragma unroll
            for (int i = 0; i < 4; i++) acc[mt][nt][i] = 0.f;

    const int nIter = K / BK;
    load_tiles(0, 0);

    for (int it = 0; it < nIter; ++it) {
        cp_wait0();
        __syncthreads();
        if (it + 1 < nIter) load_tiles((it + 1) & 1, (it + 1) * BK);
        const int buf = it & 1;

        #pragma unroll
        for (int ks = 0; ks < BK; ks += 8) {
            uint32_t af[2][4];
            #pragma unroll
            for (int mt = 0; mt < 2; mt++) {
                const int r = m0 + mt * 16 + g;
                af[mt][0] = __float_as_uint(As[buf][r]    [ks + tg]);
                af[mt][1] = __float_as_uint(As[buf][r + 8][ks + tg]);
                af[mt][2] = __float_as_uint(As[buf][r]    [ks + tg + 4]);
                af[mt][3] = __float_as_uint(As[buf][r + 8][ks + tg + 4]);
            }
            uint32_t bfr[8][2];
            #pragma unroll
            for (int nt = 0; nt < 8; nt++) {
                const int c = n0 + nt * 8 + g;
                if (TRANSB) {
                    bfr[nt][0] = __float_as_uint(Bs[buf][c][ks + tg]);
                    bfr[nt][1] = __float_as_uint(Bs[buf][c][ks + tg + 4]);
                } else {
                    bfr[nt][0] = __float_as_uint(Bs[buf][ks + tg]    [c]);
                    bfr[nt][1] = __float_as_uint(Bs[buf][ks + tg + 4][c]);
                }
            }
            #pragma unroll
            for (int mt = 0; mt < 2; mt++)
                #pragma unroll
                for (int nt = 0; nt < 8; nt++)
                    mma_tf32(acc[mt][nt], af[mt], bfr[nt]);
        }
        // no trailing sync: next iter's wait+syncthreads orders WAR on buffers
    }

    // Epilogue: alpha scale + optional bias (+ optional tf32 rounding), float2 stores
    #pragma unroll
    for (int mt = 0; mt < 2; mt++) {
        #pragma unroll
        for (int nt = 0; nt < 8; nt++) {
            const int r = m0 + mt * 16 + g;
            const int c = n0 + nt * 8 + 2 * tg;
            float b0 = 0.f, b1 = 0.f;
            if (biasp) { b0 = biasp[c]; b1 = biasp[c + 1]; }
            float2 v0, v1;
            v0.x = acc[mt][nt][0] * alpha + b0;
            v0.y = acc[mt][nt][1] * alpha + b1;
            v1.x = acc[mt][nt][2] * alpha + b0;
            v1.y = acc[mt][nt][3] * alpha + b1;
            if (roundC) {
                v0.x = tf32r(v0.x); v0.y = tf32r(v0.y);
                v1.x = tf32r(v1.x); v1.y = tf32r(v1.y);
            }
            *reinterpret_cast<float2*>(&C[(size_t)r * ldc + c])       = v0;
            *reinterpret_cast<float2*>(&C[(size_t)(r + 8) * ldc + c]) = v1;
        }
    }
}

// In-place row softmax over 4096 columns; one block (256 thr) per row.
// Output is tf32-rounded (feeds the P@V GEMM).
__global__ __launch_bounds__(256) void softmax_kernel(float* __restrict__ P)
{
    const size_t row = blockIdx.x;
    float* p = P + row * (size_t)SEQ;
    const int tid = threadIdx.x;

    float v[16];
    float mx = -1e30f;
    #pragma unroll
    for (int i = 0; i < 16; i++) {
        v[i] = p[i * 256 + tid];
        mx = fmaxf(mx, v[i]);
    }

    __shared__ float red[8];
    #pragma unroll
    for (int off = 16; off; off >>= 1)
        mx = fmaxf(mx, __shfl_xor_sync(0xFFFFFFFFu, mx, off));
    if ((tid & 31) == 0) red[tid >> 5] = mx;
    __syncthreads();
    mx = red[0];
    #pragma unroll
    for (int w = 1; w < 8; w++) mx = fmaxf(mx, red[w]);

    float sum = 0.f;
    #pragma unroll
    for (int i = 0; i < 16; i++) {
        v[i] = __expf(v[i] - mx);
        sum += v[i];
    }
    __syncthreads();
    #pragma unroll
    for (int off = 16; off; off >>= 1)
        sum += __shfl_xor_sync(0xFFFFFFFFu, sum, off);
    if ((tid & 31) == 0) red[tid >> 5] = sum;
    __syncthreads();
    sum = 0.f;
    #pragma unroll
    for (int w = 0; w < 8; w++) sum += red[w];

    const float inv = 1.f / sum;
    #pragma unroll
    for (int i = 0; i < 16; i++)
        p[i * 256 + tid] = tf32r(v[i] * inv);
}

extern "C" void kernel_launch(void* const* d_in, const int* in_sizes, int n_in,
                              void* d_out, int out_size)
{
    const float* x    = (const float*)d_in[0];
    const float* Wqkv = (const float*)d_in[1];
    const float* bqkv = (const float*)d_in[2];
    const float* Wo   = (const float*)d_in[3];
    const float* bo   = (const float*)d_in[4];
    float* out = (float*)d_out;

    float *qkv, *attn, *aout, *xt, *wqkvt, *wot;
    cudaGetSymbolAddress((void**)&qkv,   g_qkv);
    cudaGetSymbolAddress((void**)&attn,  g_attn);
    cudaGetSymbolAddress((void**)&aout,  g_out);
    cudaGetSymbolAddress((void**)&xt,    g_xt);
    cudaGetSymbolAddress((void**)&wqkvt, g_wqkvt);
    cudaGetSymbolAddress((void**)&wot,   g_wot);

    const int BS = BATCH * SEQ;                       // 16384
    const long long sQKV = (long long)SEQ * 3 * DHEAD;
    const long long sATT = (long long)SEQ * SEQ;
    const long long sOUT = (long long)SEQ * DHEAD;
    const float scale = 0.03125f;                     // 1/sqrt(1024)

    dim3 blk(256);

    // 0. tf32-round the raw inputs that feed GEMMs
    round_kernel<<<2048, 256>>>((const float4*)x,    (float4*)xt,
                                (size_t)BATCH * SEQ * HID / 4);
    round_kernel<<<1024, 256>>>((const float4*)Wqkv, (float4*)wqkvt,
                                (size_t)HID * 3 * DHEAD / 4);
    round_kernel<<<512, 256>>>((const float4*)Wo,    (float4*)wot,
                                (size_t)DHEAD * HID / 4);

    // 1. qkv = x @ Wqkv + bqkv   [16384 x 3072, K=4096]  (rounded: feeds GEMMs 2,4)
    mma_gemm<false><<<dim3((3 * DHEAD) / BN, BS / BM, 1), blk>>>(
        xt, HID, 0, wqkvt, 3 * DHEAD, 0, bqkv, qkv, 3 * DHEAD, 0, HID, 1.f, 1);

    // 2. scores = scale * Q @ K^T  (batched, 4 x [4096 x 4096, K=1024])  (fp32 out)
    mma_gemm<true><<<dim3(SEQ / BN, SEQ / BM, BATCH), blk>>>(
        qkv, 3 * DHEAD, sQKV, qkv + DHEAD, 3 * DHEAD, sQKV, nullptr,
        attn, SEQ, sATT, DHEAD, scale, 0);

    // 3. softmax rows (tf32-rounded output: feeds GEMM 4)
    softmax_kernel<<<BS, 256>>>(attn);

    // 4. out = P @ V  (batched, 4 x [4096 x 1024, K=4096])  (rounded: feeds GEMM 5)
    mma_gemm<false><<<dim3(DHEAD / BN, SEQ / BM, BATCH), blk>>>(
        attn, SEQ, sATT, qkv + 2 * DHEAD, 3 * DHEAD, sQKV, nullptr,
        aout, DHEAD, sOUT, SEQ, 1.f, 1);

    // 5. y = out @ Wo + bo   [16384 x 4096, K=1024]  (final: full fp32 out)
    mma_gemm<false><<<dim3(HID / BN, BS / BM, 1), blk>>>(
        aout, DHEAD, 0, wot, HID, 0, bo, out, HID, 0, DHEAD, 1.f, 0);
}

// round 11
// speedup vs baseline: 3.9327x; 1.1188x over previous
#include <cuda_runtime.h>
#include <cstdint>

// B=4, S=4096, H=4096, D=1024
#define BATCH 4
#define SEQ   4096
#define HID   4096
#define DHEAD 1024

// Scratch (device globals: allocation-free per harness rules)
__device__ float g_qkv  [ (size_t)BATCH * SEQ * 3 * DHEAD ];
__device__ float g_attn [ (size_t)BATCH * SEQ * SEQ       ];
__device__ float g_out  [ (size_t)BATCH * SEQ * DHEAD     ];
__device__ float g_xt   [ (size_t)BATCH * SEQ * HID       ]; // tf32-rounded x
__device__ float g_wqkvt[ (size_t)HID * 3 * DHEAD         ]; // tf32-rounded Wqkv
__device__ float g_wot  [ (size_t)DHEAD * HID             ]; // tf32-rounded Wo

#define BM 128
#define BN 128
#define BK 32
#define NSTAGE 3
#define ASTRIDE 36    // BK+4 floats: bank = (4r+tg)%32 conflict-free
#define BSTRIDE 136   // BN+8 floats: bank = (8k+c)%32 conflict-free
#define A_ST (BM * ASTRIDE)            // floats per A stage (4608)
#define B_ST_NN (BK * BSTRIDE)         // floats per B stage NN (4352)
#define B_ST_TT (BN * ASTRIDE)         // floats per B stage TT (4608)

__device__ __forceinline__ void cp_async16_s(uint32_t s, const void* g) {
    asm volatile("cp.async.cg.shared.global [%0], [%1], 16;" :: "r"(s), "l"(g));
}
__device__ __forceinline__ void cp_commit() { asm volatile("cp.async.commit_group;"); }

__device__ __forceinline__ uint32_t f2tf(float f) {
    uint32_t u; asm("cvt.rna.tf32.f32 %0, %1;" : "=r"(u) : "f"(f)); return u;
}
__device__ __forceinline__ float tf32r(float f) { return __uint_as_float(f2tf(f)); }

__device__ __forceinline__ void mma_tf32(float* c, const uint32_t* a, const uint32_t* b) {
    asm volatile(
        "mma.sync.aligned.m16n8k8.row.col.f32.tf32.tf32.f32 "
        "{%0,%1,%2,%3}, {%4,%5,%6,%7}, {%8,%9}, {%0,%1,%2,%3};"
        : "+f"(c[0]), "+f"(c[1]), "+f"(c[2]), "+f"(c[3])
        : "r"(a[0]), "r"(a[1]), "r"(a[2]), "r"(a[3]), "r"(b[0]), "r"(b[1]));
}

// Elementwise tf32 rounding pass (float4 grid-stride).
__global__ __launch_bounds__(256) void round_kernel(
    const float4* __restrict__ in, float4* __restrict__ out, size_t n4)
{
    for (size_t i = (size_t)blockIdx.x * blockDim.x + threadIdx.x; i < n4;
         i += (size_t)gridDim.x * blockDim.x) {
        float4 v = in[i];
        v.x = tf32r(v.x); v.y = tf32r(v.y); v.z = tf32r(v.z); v.w = tf32r(v.w);
        out[i] = v;
    }
}

// C[M,N] = alpha * A * op(B) (+ bias), row-major, strided batch, tf32 mma.sync.
// Inputs must be tf32-pre-rounded. 128 threads, 128x128 tile, 64x64 warp tile,
// BK=32, 3-stage cp.async pipeline, dynamic SMEM.
template <bool TRANSB>
__global__ __launch_bounds__(128) void mma_gemm(
    const float* __restrict__ A, int lda, long long sA,
    const float* __restrict__ B, int ldb, long long sB,
    const float* __restrict__ bias,
    float* __restrict__ C, int ldc, long long sC,
    int K, float alpha, int roundC)
{
    extern __shared__ float sm[];
    float* As = sm;                               // NSTAGE * A_ST
    float* Bs = sm + NSTAGE * A_ST;               // NSTAGE * B_ST

    const int tid = threadIdx.x;
    const int bx = blockIdx.x, by = blockIdx.y, bz = blockIdx.z;

    const float* Ag = A + (long long)bz * sA + (size_t)by * BM * lda;
    const float* Bg;
    if (TRANSB) Bg = B + (long long)bz * sB + (size_t)bx * BN * ldb;
    else        Bg = B + (long long)bz * sB + (size_t)bx * BN;

    const uint32_t smA = (uint32_t)__cvta_generic_to_shared(As);
    const uint32_t smB = (uint32_t)__cvta_generic_to_shared(Bs);

    // Loader: 128 threads, 8 chunks of 16B per array per stage
    auto load_stage = [&](int st, int k0) {
        #pragma unroll
        for (int i = 0; i < 8; i++) {
            const int ch = tid + i * 128;             // 0..1023
            const int r = ch >> 3, kq = (ch & 7) * 4; // A: row, k-offset
            cp_async16_s(smA + 4u * (st * A_ST + r * ASTRIDE + kq),
                         Ag + (size_t)r * lda + k0 + kq);
        }
        if (TRANSB) {
            #pragma unroll
            for (int i = 0; i < 8; i++) {
                const int ch = tid + i * 128;
                const int r = ch >> 3, kq = (ch & 7) * 4;
                cp_async16_s(smB + 4u * (st * B_ST_TT + r * ASTRIDE + kq),
                             Bg + (size_t)r * ldb + k0 + kq);
            }
        } else {
            #pragma unroll
            for (int i = 0; i < 8; i++) {
                const int ch = tid + i * 128;
                const int r = ch >> 5, cq = (ch & 31) * 4;
                cp_async16_s(smB + 4u * (st * B_ST_NN + r * BSTRIDE + cq),
                             Bg + (size_t)(k0 + r) * ldb + cq);
            }
        }
        cp_commit();
    };

    // Warp tiling: 4 warps as 2(M) x 2(N); warp tile 64x64
    const int lane = tid & 31;
    const int wid  = tid >> 5;
    const int m0 = (wid & 1) * 64;
    const int n0 = (wid >> 1) * 64;
    const int g  = lane >> 2;
    const int tg = lane & 3;

    float acc[4][8][4];
    #pragma unroll
    for (int mt = 0; mt < 4; mt++)
        #pragma unroll
        for (int nt = 0; nt < 8; nt++)
            #pragma unroll
            for (int i = 0; i < 4; i++) acc[mt][nt][i] = 0.f;

    const int nIter = K / BK;
    load_stage(0, 0);
    load_stage(1, BK);

    for (int it = 0; it < nIter; ++it) {
        if (it + 1 < nIter)
            asm volatile("cp.async.wait_group 1;");
        else
            asm volatile("cp.async.wait_group 0;");
        __syncthreads();
        if (it + 2 < nIter) load_stage((it + 2) % NSTAGE, (it + 2) * BK);

        const float* as = As + (it % NSTAGE) * A_ST;
        const float* bs = Bs + (it % NSTAGE) * (TRANSB ? B_ST_TT : B_ST_NN);

        #pragma unroll
        for (int ks = 0; ks < BK; ks += 8) {
            uint32_t af[4][4];
            #pragma unroll
            for (int mt = 0; mt < 4; mt++) {
                const int r = m0 + mt * 16 + g;
                af[mt][0] = __float_as_uint(as[(r)     * ASTRIDE + ks + tg]);
                af[mt][1] = __float_as_uint(as[(r + 8) * ASTRIDE + ks + tg]);
                af[mt][2] = __float_as_uint(as[(r)     * ASTRIDE + ks + tg + 4]);
                af[mt][3] = __float_as_uint(as[(r + 8) * ASTRIDE + ks + tg + 4]);
            }
            uint32_t bfr[8][2];
            #pragma unroll
            for (int nt = 0; nt < 8; nt++) {
                const int c = n0 + nt * 8 + g;
                if (TRANSB) {
                    bfr[nt][0] = __float_as_uint(bs[c * ASTRIDE + ks + tg]);
                    bfr[nt][1] = __float_as_uint(bs[c * ASTRIDE + ks + tg + 4]);
                } else {
                    bfr[nt][0] = __float_as_uint(bs[(ks + tg)     * BSTRIDE + c]);
                    bfr[nt][1] = __float_as_uint(bs[(ks + tg + 4) * BSTRIDE + c]);
                }
            }
            #pragma unroll
            for (int mt = 0; mt < 4; mt++)
                #pragma unroll
                for (int nt = 0; nt < 8; nt++)
                    mma_tf32(acc[mt][nt], af[mt], bfr[nt]);
        }
        __syncthreads();   // readers done before stage (it+3) overwrites this buf
    }

    // Epilogue
    float* Cg = C + (long long)bz * sC + (size_t)by * BM * ldc + (size_t)bx * BN;
    const float* biasp = bias ? (bias + (size_t)bx * BN) : nullptr;
    #pragma unroll
    for (int mt = 0; mt < 4; mt++) {
        #pragma unroll
        for (int nt = 0; nt < 8; nt++) {
            const int r = m0 + mt * 16 + g;
            const int c = n0 + nt * 8 + 2 * tg;
            float b0 = 0.f, b1 = 0.f;
            if (biasp) { b0 = biasp[c]; b1 = biasp[c + 1]; }
            float2 v0, v1;
            v0.x = acc[mt][nt][0] * alpha + b0;
            v0.y = acc[mt][nt][1] * alpha + b1;
            v1.x = acc[mt][nt][2] * alpha + b0;
            v1.y = acc[mt][nt][3] * alpha + b1;
            if (roundC) {
                v0.x = tf32r(v0.x); v0.y = tf32r(v0.y);
                v1.x = tf32r(v1.x); v1.y = tf32r(v1.y);
            }
            *reinterpret_cast<float2*>(&Cg[(size_t)r * ldc + c])       = v0;
            *reinterpret_cast<float2*>(&Cg[(size_t)(r + 8) * ldc + c]) = v1;
        }
    }
}

// In-place row softmax over 4096 columns; one block (256 thr) per row.
// Output tf32-rounded (feeds P@V GEMM).
__global__ __launch_bounds__(256) void softmax_kernel(float* __restrict__ P)
{
    const size_t row = blockIdx.x;
    float* p = P + row * (size_t)SEQ;
    const int tid = threadIdx.x;

    float v[16];
    float mx = -1e30f;
    #pragma unroll
    for (int i = 0; i < 16; i++) { v[i] = p[i * 256 + tid]; mx = fmaxf(mx, v[i]); }

    __shared__ float red[8];
    #pragma unroll
    for (int off = 16; off; off >>= 1)
        mx = fmaxf(mx, __shfl_xor_sync(0xFFFFFFFFu, mx, off));
    if ((tid & 31) == 0) red[tid >> 5] = mx;
    __syncthreads();
    mx = red[0];
    #pragma unroll
    for (int w = 1; w < 8; w++) mx = fmaxf(mx, red[w]);

    float sum = 0.f;
    #pragma unroll
    for (int i = 0; i < 16; i++) { v[i] = __expf(v[i] - mx); sum += v[i]; }
    __syncthreads();
    #pragma unroll
    for (int off = 16; off; off >>= 1)
        sum += __shfl_xor_sync(0xFFFFFFFFu, sum, off);
    if ((tid & 31) == 0) red[tid >> 5] = sum;
    __syncthreads();
    sum = 0.f;
    #pragma unroll
    for (int w = 0; w < 8; w++) sum += red[w];

    const float inv = 1.f / sum;
    #pragma unroll
    for (int i = 0; i < 16; i++)
        p[i * 256 + tid] = tf32r(v[i] * inv);
}

extern "C" void kernel_launch(void* const* d_in, const int* in_sizes, int n_in,
                              void* d_out, int out_size)
{
    const float* x    = (const float*)d_in[0];
    const float* Wqkv = (const float*)d_in[1];
    const float* bqkv = (const float*)d_in[2];
    const float* Wo   = (const float*)d_in[3];
    const float* bo   = (const float*)d_in[4];
    float* out = (float*)d_out;

    float *qkv, *attn, *aout, *xt, *wqkvt, *wot;
    cudaGetSymbolAddress((void**)&qkv,   g_qkv);
    cudaGetSymbolAddress((void**)&attn,  g_attn);
    cudaGetSymbolAddress((void**)&aout,  g_out);
    cudaGetSymbolAddress((void**)&xt,    g_xt);
    cudaGetSymbolAddress((void**)&wqkvt, g_wqkvt);
    cudaGetSymbolAddress((void**)&wot,   g_wot);

    // Dynamic SMEM: NSTAGE * (A_ST + max(B_ST)) floats
    const int SMEM_DYN = NSTAGE * (A_ST + B_ST_TT) * 4;   // 110592 B
    cudaFuncSetAttribute(mma_gemm<false>, cudaFuncAttributeMaxDynamicSharedMemorySize, SMEM_DYN);
    cudaFuncSetAttribute(mma_gemm<true>,  cudaFuncAttributeMaxDynamicSharedMemorySize, SMEM_DYN);

    const int BS = BATCH * SEQ;                       // 16384
    const long long sQKV = (long long)SEQ * 3 * DHEAD;
    const long long sATT = (long long)SEQ * SEQ;
    const long long sOUT = (long long)SEQ * DHEAD;
    const float scale = 0.03125f;                     // 1/sqrt(1024)
    dim3 blk(128);

    // 0. tf32-round raw GEMM inputs
    round_kernel<<<2048, 256>>>((const float4*)x,    (float4*)xt,
                                (size_t)BATCH * SEQ * HID / 4);
    round_kernel<<<1024, 256>>>((const float4*)Wqkv, (float4*)wqkvt,
                                (size_t)HID * 3 * DHEAD / 4);
    round_kernel<<<512, 256>>>((const float4*)Wo,    (float4*)wot,
                                (size_t)DHEAD * HID / 4);

    // 1. qkv = x @ Wqkv + bqkv   [16384 x 3072, K=4096]  (rounded out)
    mma_gemm<false><<<dim3((3 * DHEAD) / BN, BS / BM, 1), blk, SMEM_DYN>>>(
        xt, HID, 0, wqkvt, 3 * DHEAD, 0, bqkv, qkv, 3 * DHEAD, 0, HID, 1.f, 1);

    // 2. scores = scale * Q @ K^T  (batched, K=1024)  (fp32 out)
    mma_gemm<true><<<dim3(SEQ / BN, SEQ / BM, BATCH), blk, SMEM_DYN>>>(
        qkv, 3 * DHEAD, sQKV, qkv + DHEAD, 3 * DHEAD, sQKV, nullptr,
        attn, SEQ, sATT, DHEAD, scale, 0);

    // 3. softmax rows (tf32-rounded out)
    softmax_kernel<<<BS, 256>>>(attn);

    // 4. out = P @ V  (batched, K=4096)  (rounded out)
    mma_gemm<false><<<dim3(DHEAD / BN, SEQ / BM, BATCH), blk, SMEM_DYN>>>(
        attn, SEQ, sATT, qkv + 2 * DHEAD, 3 * DHEAD, sQKV, nullptr,
        aout, DHEAD, sOUT, SEQ, 1.f, 1);

    // 5. y = out @ Wo + bo   [16384 x 4096, K=1024]
    mma_gemm<false><<<dim3(HID / BN, BS / BM, 1), blk, SMEM_DYN>>>(
        aout, DHEAD, 0, wot, HID, 0, bo, out, HID, 0, DHEAD, 1.f, 0);
}

// round 13
// speedup vs baseline: 8.8730x; 2.2562x over previous
#include <cuda_runtime.h>
#include <cuda_fp16.h>
#include <cstdint>

// B=4, S=4096, H=4096, D=1024
#define BATCH 4
#define SEQ   4096
#define HID   4096
#define DHEAD 1024

// Scratch (device globals: allocation-free per harness rules)
__device__ __align__(16) __half g_xh    [ (size_t)BATCH * SEQ * HID   ]; // 134 MB fp16 x
__device__ __align__(16) __half g_wqkvT [ (size_t)3 * DHEAD * HID     ]; //  25 MB Wqkv^T fp16
__device__ __align__(16) __half g_woT   [ (size_t)HID * DHEAD         ]; //   8 MB Wo^T fp16
__device__ __align__(16) __half g_qkvh  [ (size_t)BATCH * SEQ * 3 * DHEAD ]; // 100 MB (q,k used)
__device__ __align__(16) __half g_vth   [ (size_t)BATCH * DHEAD * SEQ ]; //  33 MB V^T fp16
__device__ float                g_attn  [ (size_t)BATCH * SEQ * SEQ   ]; // 268 MB fp32 scores
__device__ __align__(16) __half g_attnh [ (size_t)BATCH * SEQ * SEQ   ]; // 134 MB fp16 P
__device__ __align__(16) __half g_aouth [ (size_t)BATCH * SEQ * DHEAD ]; //  33 MB fp16 attn-out

#define BM 128
#define BN 128
#define BK 64
#define NSTAGE 3
#define STAGE_BYTES 32768      // A 16KB + B 16KB (half, 128 rows x 128B)

__device__ __forceinline__ uint32_t h2_bits(__half2 h) {
    return *reinterpret_cast<uint32_t*>(&h);
}

__device__ __forceinline__ void cp_async16_s(uint32_t s, const void* g) {
    asm volatile("cp.async.cg.shared.global [%0], [%1], 16;" :: "r"(s), "l"(g));
}
__device__ __forceinline__ void cp_commit() { asm volatile("cp.async.commit_group;"); }

__device__ __forceinline__ void ldsm4(uint32_t& r0, uint32_t& r1, uint32_t& r2,
                                      uint32_t& r3, uint32_t a) {
    asm volatile("ldmatrix.sync.aligned.m8n8.x4.shared.b16 {%0,%1,%2,%3}, [%4];"
                 : "=r"(r0), "=r"(r1), "=r"(r2), "=r"(r3) : "r"(a));
}

__device__ __forceinline__ void mma_f16(float* c, const uint32_t* a, const uint32_t* b) {
    asm volatile(
        "mma.sync.aligned.m16n8k16.row.col.f32.f16.f16.f32 "
        "{%0,%1,%2,%3}, {%4,%5,%6,%7}, {%8,%9}, {%0,%1,%2,%3};"
        : "+f"(c[0]), "+f"(c[1]), "+f"(c[2]), "+f"(c[3])
        : "r"(a[0]), "r"(a[1]), "r"(a[2]), "r"(a[3]), "r"(b[0]), "r"(b[1]));
}

// NT fp16 GEMM: C[M,N] = alpha * A(K-major) . B^T (B stored [N,K] K-major) (+bias)
// CTA 128x128, 4 warps (64x64 each), BK=64, 3-stage cp.async, SW128 swizzle, ldmatrix.
// MODE 0: fp32 C32.  MODE 1: fp16 C16.  MODE 2: qkv split (n<2048 -> C16; v -> VT^T).
template <int MODE>
__global__ __launch_bounds__(128) void hgemm(
    const __half* __restrict__ A, int lda, long long sA,
    const __half* __restrict__ B, int ldb, long long sB,
    const float* __restrict__ bias,
    float* __restrict__ C32, __half* __restrict__ C16, __half* __restrict__ VT,
    int ldc, long long sC, int K, float alpha)
{
    extern __shared__ char dsm[];
    const uint32_t smBase = (uint32_t)__cvta_generic_to_shared(dsm);

    const int tid = threadIdx.x;
    const int bx = blockIdx.x, by = blockIdx.y, bz = blockIdx.z;

    const __half* Ag = A + (long long)bz * sA + (size_t)by * BM * lda;
    const __half* Bg = B + (long long)bz * sB + (size_t)bx * BN * ldb;

    // Loader: per stage, A and B each 128 rows x 8 16B-chunks; 8 cp.async each per thread
    auto load_stage = [&](int st, int k0) {
        const uint32_t sa = smBase + st * STAGE_BYTES;
        const uint32_t sb = sa + 16384;
        #pragma unroll
        for (int i = 0; i < 8; i++) {
            const int ch = tid + i * 128;
            const int r = ch >> 3, c = ch & 7;
            cp_async16_s(sa + (uint32_t)(r * 128 + ((c ^ (r & 7)) << 4)),
                         Ag + (size_t)r * lda + k0 + c * 8);
        }
        #pragma unroll
        for (int i = 0; i < 8; i++) {
            const int ch = tid + i * 128;
            const int r = ch >> 3, c = ch & 7;
            cp_async16_s(sb + (uint32_t)(r * 128 + ((c ^ (r & 7)) << 4)),
                         Bg + (size_t)r * ldb + k0 + c * 8);
        }
        cp_commit();
    };

    // 4 warps as 2(M) x 2(N); warp tile 64x64
    const int lane = tid & 31;
    const int wid  = tid >> 5;
    const int m0 = (wid & 1) * 64;
    const int n0 = (wid >> 1) * 64;
    const int g  = lane >> 2;
    const int tg = lane & 3;
    const int sub = lane & 7;

    float acc[4][8][4];
    #pragma unroll
    for (int mt = 0; mt < 4; mt++)
        #pragma unroll
        for (int nt = 0; nt < 8; nt++)
            #pragma unroll
            for (int i = 0; i < 4; i++) acc[mt][nt][i] = 0.f;

    const int nIter = K / BK;
    load_stage(0, 0);
    load_stage(1, BK);

    for (int it = 0; it < nIter; ++it) {
        if (it + 1 < nIter) asm volatile("cp.async.wait_group 1;");
        else                asm volatile("cp.async.wait_group 0;");
        __syncthreads();
        if (it + 2 < nIter) load_stage((it + 2) % NSTAGE, (it + 2) * BK);

        const uint32_t sa = smBase + (it % NSTAGE) * STAGE_BYTES;
        const uint32_t sb = sa + 16384;

        #pragma unroll
        for (int ks4 = 0; ks4 < 4; ks4++) {          // k16 slice = ks4*16
            // A fragments: lane j=lane>>3 -> (m-block j&1, k-chunk j>>1)
            uint32_t af[4][4];
            #pragma unroll
            for (int mt = 0; mt < 4; mt++) {
                const int row = m0 + mt * 16 + ((lane >> 3) & 1) * 8 + sub;
                const int chunk = 2 * ks4 + (lane >> 4);
                ldsm4(af[mt][0], af[mt][1], af[mt][2], af[mt][3],
                      sa + (uint32_t)(row * 128 + ((chunk ^ (row & 7)) << 4)));
            }
            // B fragments: lane j -> (n-block j>>1, k-chunk j&1); x4 covers 2 nt
            uint32_t bf[8][2];
            #pragma unroll
            for (int p = 0; p < 4; p++) {
                const int row = n0 + p * 16 + (lane >> 4) * 8 + sub;
                const int chunk = 2 * ks4 + ((lane >> 3) & 1);
                ldsm4(bf[2 * p][0], bf[2 * p][1], bf[2 * p + 1][0], bf[2 * p + 1][1],
                      sb + (uint32_t)(row * 128 + ((chunk ^ (row & 7)) << 4)));
            }
            #pragma unroll
            for (int mt = 0; mt < 4; mt++)
                #pragma unroll
                for (int nt = 0; nt < 8; nt++)
                    mma_f16(acc[mt][nt], af[mt], bf[nt]);
        }
        __syncthreads();
    }

    // Epilogue
    const bool is_v = (MODE == 2) && (bx >= 16);     // v region: n >= 2048 (16*128)
    #pragma unroll
    for (int mt = 0; mt < 4; mt++) {
        #pragma unroll
        for (int nt = 0; nt < 8; nt++) {
            const int r = m0 + mt * 16 + g;
            const int c = n0 + nt * 8 + 2 * tg;
            const int nglob = bx * BN + c;
            float b0 = 0.f, b1 = 0.f;
            if (bias) { b0 = bias[nglob]; b1 = bias[nglob + 1]; }
            const float v00 = acc[mt][nt][0] * alpha + b0;
            const float v01 = acc[mt][nt][1] * alpha + b1;
            const float v10 = acc[mt][nt][2] * alpha + b0;
            const float v11 = acc[mt][nt][3] * alpha + b1;
            const int m_lo = by * BM + r, m_hi = m_lo + 8;
            if (MODE == 0) {
                float* Cg = C32 + (long long)bz * sC;
                *reinterpret_cast<float2*>(&Cg[(size_t)m_lo * ldc + nglob]) =
                    make_float2(v00, v01);
                *reinterpret_cast<float2*>(&Cg[(size_t)m_hi * ldc + nglob]) =
                    make_float2(v10, v11);
            } else if (MODE == 1 || !is_v) {
                __half* Cg = C16 + (long long)bz * sC;
                *reinterpret_cast<__half2*>(&Cg[(size_t)m_lo * ldc + nglob]) =
                    __floats2half2_rn(v00, v01);
                *reinterpret_cast<__half2*>(&Cg[(size_t)m_hi * ldc + nglob]) =
                    __floats2half2_rn(v10, v11);
            } else {
                // V region: write V^T [b][d][s]
                const int d = nglob - 2048;
                const int b_lo = m_lo >> 12, s_lo = m_lo & 4095;
                const int b_hi = m_hi >> 12, s_hi = m_hi & 4095;
                VT[((size_t)b_lo * DHEAD + d)     * SEQ + s_lo] = __float2half_rn(v00);
                VT[((size_t)b_lo * DHEAD + d + 1) * SEQ + s_lo] = __float2half_rn(v01);
                VT[((size_t)b_hi * DHEAD + d)     * SEQ + s_hi] = __float2half_rn(v10);
                VT[((size_t)b_hi * DHEAD + d + 1) * SEQ + s_hi] = __float2half_rn(v11);
            }
        }
    }
}

// fp32 -> fp16 elementwise (float4 -> 2x half2), grid-stride
__global__ __launch_bounds__(256) void f2h_kernel(
    const float4* __restrict__ in, uint2* __restrict__ out, size_t n4)
{
    for (size_t i = (size_t)blockIdx.x * blockDim.x + threadIdx.x; i < n4;
         i += (size_t)gridDim.x * blockDim.x) {
        float4 v = in[i];
        uint2 o;
        o.x = h2_bits(__floats2half2_rn(v.x, v.y));
        o.y = h2_bits(__floats2half2_rn(v.z, v.w));
        out[i] = o;
    }
}

// out_h[c][r] = half(in[r][c]); R, C multiples of 32
__global__ __launch_bounds__(256) void transpose_f2h(
    const float* __restrict__ in, __half* __restrict__ out, int R, int C)
{
    __shared__ float t[32][33];
    const int c = blockIdx.x * 32 + threadIdx.x;
    const int r0 = blockIdx.y * 32;
    for (int i = threadIdx.y; i < 32; i += 8)
        t[i][threadIdx.x] = in[(size_t)(r0 + i) * C + c];
    __syncthreads();
    const int rr = r0 + threadIdx.x;
    const int cc = blockIdx.x * 32;
    for (int i = threadIdx.y; i < 32; i += 8)
        out[(size_t)(cc + i) * R + rr] = __float2half_rn(t[threadIdx.x][i]);
}

// Row softmax over 4096 cols: read fp32 scores, write fp16 P. One block per row.
__global__ __launch_bounds__(256) void softmax_h(
    const float* __restrict__ P, __half* __restrict__ Ph)
{
    const size_t row = blockIdx.x;
    const float2* p2 = reinterpret_cast<const float2*>(P + row * (size_t)SEQ);
    __half2* o2 = reinterpret_cast<__half2*>(Ph + row * (size_t)SEQ);
    const int tid = threadIdx.x;

    float2 v[8];
    float mx = -1e30f;
    #pragma unroll
    for (int i = 0; i < 8; i++) {
        v[i] = p2[i * 256 + tid];
        mx = fmaxf(mx, fmaxf(v[i].x, v[i].y));
    }

    __shared__ float red[8];
    #pragma unroll
    for (int off = 16; off; off >>= 1)
        mx = fmaxf(mx, __shfl_xor_sync(0xFFFFFFFFu, mx, off));
    if ((tid & 31) == 0) red[tid >> 5] = mx;
    __syncthreads();
    mx = red[0];
    #pragma unroll
    for (int w = 1; w < 8; w++) mx = fmaxf(mx, red[w]);

    float sum = 0.f;
    #pragma unroll
    for (int i = 0; i < 8; i++) {
        v[i].x = __expf(v[i].x - mx);
        v[i].y = __expf(v[i].y - mx);
        sum += v[i].x + v[i].y;
    }
    __syncthreads();
    #pragma unroll
    for (int off = 16; off; off >>= 1)
        sum += __shfl_xor_sync(0xFFFFFFFFu, sum, off);
    if ((tid & 31) == 0) red[tid >> 5] = sum;
    __syncthreads();
    sum = 0.f;
    #pragma unroll
    for (int w = 0; w < 8; w++) sum += red[w];

    const float inv = 1.f / sum;
    #pragma unroll
    for (int i = 0; i < 8; i++)
        o2[i * 256 + tid] = __floats2half2_rn(v[i].x * inv, v[i].y * inv);
}

extern "C" void kernel_launch(void* const* d_in, const int* in_sizes, int n_in,
                              void* d_out, int out_size)
{
    const float* x    = (const float*)d_in[0];
    const float* Wqkv = (const float*)d_in[1];
    const float* bqkv = (const float*)d_in[2];
    const float* Wo   = (const float*)d_in[3];
    const float* bo   = (const float*)d_in[4];
    float* out = (float*)d_out;

    __half *xh, *wqkvT, *woT, *qkvh, *vth, *attnh, *aouth;
    float *attn;
    cudaGetSymbolAddress((void**)&xh,    g_xh);
    cudaGetSymbolAddress((void**)&wqkvT, g_wqkvT);
    cudaGetSymbolAddress((void**)&woT,   g_woT);
    cudaGetSymbolAddress((void**)&qkvh,  g_qkvh);
    cudaGetSymbolAddress((void**)&vth,   g_vth);
    cudaGetSymbolAddress((void**)&attn,  g_attn);
    cudaGetSymbolAddress((void**)&attnh, g_attnh);
    cudaGetSymbolAddress((void**)&aouth, g_aouth);

    const int SMEM_DYN = NSTAGE * STAGE_BYTES;   // 98304 B
    cudaFuncSetAttribute(hgemm<0>, cudaFuncAttributeMaxDynamicSharedMemorySize, SMEM_DYN);
    cudaFuncSetAttribute(hgemm<1>, cudaFuncAttributeMaxDynamicSharedMemorySize, SMEM_DYN);
    cudaFuncSetAttribute(hgemm<2>, cudaFuncAttributeMaxDynamicSharedMemorySize, SMEM_DYN);

    const int BS = BATCH * SEQ;                      // 16384
    const long long sQKV = (long long)SEQ * 3 * DHEAD;
    const long long sATT = (long long)SEQ * SEQ;
    const long long sVT  = (long long)DHEAD * SEQ;
    const long long sOUT = (long long)SEQ * DHEAD;
    const float scale = 0.03125f;                    // 1/sqrt(1024)
    dim3 blk(128);

    // 0. fp16 conversions: x (elementwise), Wqkv^T and Wo^T (transpose)
    f2h_kernel<<<2048, 256>>>((const float4*)x, (uint2*)xh,
                              (size_t)BS * HID / 4);
    transpose_f2h<<<dim3(3 * DHEAD / 32, HID / 32), dim3(32, 8)>>>(Wqkv, wqkvT, HID, 3 * DHEAD);
    transpose_f2h<<<dim3(HID / 32, DHEAD / 32), dim3(32, 8)>>>(Wo, woT, DHEAD, HID);

    // 1. qkv = x @ Wqkv + bqkv  [16384 x 3072, K=4096]; q,k -> qkvh, v -> vth^T
    hgemm<2><<<dim3(3 * DHEAD / BN, BS / BM, 1), blk, SMEM_DYN>>>(
        xh, HID, 0, wqkvT, HID, 0, bqkv,
        nullptr, qkvh, vth, 3 * DHEAD, 0, HID, 1.f);

    // 2. scores = scale * Q @ K^T  (batched, K=1024) -> fp32 attn
    hgemm<0><<<dim3(SEQ / BN, SEQ / BM, BATCH), blk, SMEM_DYN>>>(
        qkvh, 3 * DHEAD, sQKV, qkvh + DHEAD, 3 * DHEAD, sQKV, nullptr,
        attn, nullptr, nullptr, SEQ, sATT, DHEAD, scale);

    // 3. softmax rows -> fp16 P
    softmax_h<<<BS, 256>>>(attn, attnh);

    // 4. out = P @ V  (batched, K=4096; B = V^T [1024][4096]) -> fp16 aout
    hgemm<1><<<dim3(DHEAD / BN, SEQ / BM, BATCH), blk, SMEM_DYN>>>(
        attnh, SEQ, sATT, vth, SEQ, sVT, nullptr,
        nullptr, aouth, nullptr, DHEAD, sOUT, SEQ, 1.f);

    // 5. y = out @ Wo + bo  [16384 x 4096, K=1024] -> fp32
    hgemm<0><<<dim3(HID / BN, BS / BM, 1), blk, SMEM_DYN>>>(
        aouth, DHEAD, 0, woT, DHEAD, 0, bo,
        out, nullptr, nullptr, HID, 0, DHEAD, 1.f);
}

// round 14
// speedup vs baseline: 9.3433x; 1.0530x over previous
#include <cuda_runtime.h>
#include <cuda_fp16.h>
#include <cstdint>

// B=4, S=4096, H=4096, D=1024
#define BATCH 4
#define SEQ   4096
#define HID   4096
#define DHEAD 1024

// Scratch (device globals: allocation-free per harness rules)
__device__ __align__(16) __half g_xh    [ (size_t)BATCH * SEQ * HID   ]; // 134 MB fp16 x
__device__ __align__(16) __half g_wqkvT [ (size_t)3 * DHEAD * HID     ]; //  25 MB Wqkv^T fp16
__device__ __align__(16) __half g_woT   [ (size_t)HID * DHEAD         ]; //   8 MB Wo^T fp16
__device__ __align__(16) __half g_qkvh  [ (size_t)BATCH * SEQ * 3 * DHEAD ]; // 100 MB (q,k used)
__device__ __align__(16) __half g_vth   [ (size_t)BATCH * DHEAD * SEQ ]; //  33 MB V^T fp16
__device__ float                g_attn  [ (size_t)BATCH * SEQ * SEQ   ]; // 268 MB fp32 scores
__device__ __align__(16) __half g_attnh [ (size_t)BATCH * SEQ * SEQ   ]; // 134 MB fp16 P
__device__ __align__(16) __half g_aouth [ (size_t)BATCH * SEQ * DHEAD ]; //  33 MB fp16 attn-out

#define BM 128
#define BN 128
#define BK 64
#define NSTAGE 3
#define STAGE_BYTES 32768      // A 16KB + B 16KB (half, 128 rows x 128B)

__device__ __forceinline__ uint32_t h2_bits(__half2 h) {
    return *reinterpret_cast<uint32_t*>(&h);
}

__device__ __forceinline__ void cp_async16_s(uint32_t s, const void* g) {
    asm volatile("cp.async.cg.shared.global [%0], [%1], 16;" :: "r"(s), "l"(g));
}
__device__ __forceinline__ void cp_commit() { asm volatile("cp.async.commit_group;"); }

__device__ __forceinline__ void ldsm4(uint32_t& r0, uint32_t& r1, uint32_t& r2,
                                      uint32_t& r3, uint32_t a) {
    asm volatile("ldmatrix.sync.aligned.m8n8.x4.shared.b16 {%0,%1,%2,%3}, [%4];"
                 : "=r"(r0), "=r"(r1), "=r"(r2), "=r"(r3) : "r"(a));
}

__device__ __forceinline__ void mma_f16(float* c, const uint32_t* a, const uint32_t* b) {
    asm volatile(
        "mma.sync.aligned.m16n8k16.row.col.f32.f16.f16.f32 "
        "{%0,%1,%2,%3}, {%4,%5,%6,%7}, {%8,%9}, {%0,%1,%2,%3};"
        : "+f"(c[0]), "+f"(c[1]), "+f"(c[2]), "+f"(c[3])
        : "r"(a[0]), "r"(a[1]), "r"(a[2]), "r"(a[3]), "r"(b[0]), "r"(b[1]));
}

// NT fp16 GEMM: C[M,N] = alpha * A(K-major) . B^T (B stored [N,K] K-major) (+bias)
// CTA 128x128, 256 threads / 8 warps (warp tile 64x32), BK=64, 3-stage cp.async,
// SW128 swizzle + ldmatrix. One barrier per mainloop iter.
// MODE 0: fp32 C32.  MODE 1: fp16 C16.  MODE 2: qkv split (n<2048 -> C16; v -> VT^T).
template <int MODE>
__global__ __launch_bounds__(256, 2) void hgemm(
    const __half* __restrict__ A, int lda, long long sA,
    const __half* __restrict__ B, int ldb, long long sB,
    const float* __restrict__ bias,
    float* __restrict__ C32, __half* __restrict__ C16, __half* __restrict__ VT,
    int ldc, long long sC, int K, float alpha)
{
    extern __shared__ char dsm[];
    const uint32_t smBase = (uint32_t)__cvta_generic_to_shared(dsm);

    const int tid = threadIdx.x;
    const int bx = blockIdx.x, by = blockIdx.y, bz = blockIdx.z;

    const __half* Ag = A + (long long)bz * sA + (size_t)by * BM * lda;
    const __half* Bg = B + (long long)bz * sB + (size_t)bx * BN * ldb;

    // Loader: per stage, A and B each 1024 16B-chunks; 4 per thread per array
    auto load_stage = [&](int st, int k0) {
        const uint32_t sa = smBase + st * STAGE_BYTES;
        const uint32_t sb = sa + 16384;
        #pragma unroll
        for (int i = 0; i < 4; i++) {
            const int ch = tid + i * 256;
            const int r = ch >> 3, c = ch & 7;
            cp_async16_s(sa + (uint32_t)(r * 128 + ((c ^ (r & 7)) << 4)),
                         Ag + (size_t)r * lda + k0 + c * 8);
        }
        #pragma unroll
        for (int i = 0; i < 4; i++) {
            const int ch = tid + i * 256;
            const int r = ch >> 3, c = ch & 7;
            cp_async16_s(sb + (uint32_t)(r * 128 + ((c ^ (r & 7)) << 4)),
                         Bg + (size_t)r * ldb + k0 + c * 8);
        }
        cp_commit();
    };

    // 8 warps as 2(M) x 4(N); warp tile 64x32
    const int lane = tid & 31;
    const int wid  = tid >> 5;
    const int m0 = (wid & 1) * 64;
    const int n0 = (wid >> 1) * 32;
    const int g  = lane >> 2;
    const int tg = lane & 3;
    const int sub = lane & 7;

    float acc[4][4][4];
    #pragma unroll
    for (int mt = 0; mt < 4; mt++)
        #pragma unroll
        for (int nt = 0; nt < 4; nt++)
            #pragma unroll
            for (int i = 0; i < 4; i++) acc[mt][nt][i] = 0.f;

    const int nIter = K / BK;
    load_stage(0, 0);
    load_stage(1, BK);

    for (int it = 0; it < nIter; ++it) {
        if (it + 1 < nIter) asm volatile("cp.async.wait_group 1;");
        else                asm volatile("cp.async.wait_group 0;");
        __syncthreads();   // single barrier: orders stage-(it) RAW and stage-(it+2) WAR
        if (it + 2 < nIter) load_stage((it + 2) % NSTAGE, (it + 2) * BK);

        const uint32_t sa = smBase + (it % NSTAGE) * STAGE_BYTES;
        const uint32_t sb = sa + 16384;

        #pragma unroll
        for (int ks4 = 0; ks4 < 4; ks4++) {          // k16 slice = ks4*16
            uint32_t af[4][4];
            #pragma unroll
            for (int mt = 0; mt < 4; mt++) {
                const int row = m0 + mt * 16 + ((lane >> 3) & 1) * 8 + sub;
                const int chunk = 2 * ks4 + (lane >> 4);
                ldsm4(af[mt][0], af[mt][1], af[mt][2], af[mt][3],
                      sa + (uint32_t)(row * 128 + ((chunk ^ (row & 7)) << 4)));
            }
            uint32_t bf[4][2];
            #pragma unroll
            for (int p = 0; p < 2; p++) {
                const int row = n0 + p * 16 + (lane >> 4) * 8 + sub;
                const int chunk = 2 * ks4 + ((lane >> 3) & 1);
                ldsm4(bf[2 * p][0], bf[2 * p][1], bf[2 * p + 1][0], bf[2 * p + 1][1],
                      sb + (uint32_t)(row * 128 + ((chunk ^ (row & 7)) << 4)));
            }
            #pragma unroll
            for (int mt = 0; mt < 4; mt++)
                #pragma unroll
                for (int nt = 0; nt < 4; nt++)
                    mma_f16(acc[mt][nt], af[mt], bf[nt]);
        }
    }

    // Epilogue
    const bool is_v = (MODE == 2) && (bx >= 16);     // v region: n >= 2048 (16*128)
    #pragma unroll
    for (int mt = 0; mt < 4; mt++) {
        #pragma unroll
        for (int nt = 0; nt < 4; nt++) {
            const int r = m0 + mt * 16 + g;
            const int c = n0 + nt * 8 + 2 * tg;
            const int nglob = bx * BN + c;
            float b0 = 0.f, b1 = 0.f;
            if (bias) { b0 = bias[nglob]; b1 = bias[nglob + 1]; }
            const float v00 = acc[mt][nt][0] * alpha + b0;
            const float v01 = acc[mt][nt][1] * alpha + b1;
            const float v10 = acc[mt][nt][2] * alpha + b0;
            const float v11 = acc[mt][nt][3] * alpha + b1;
            const int m_lo = by * BM + r, m_hi = m_lo + 8;
            if (MODE == 0) {
                float* Cg = C32 + (long long)bz * sC;
                *reinterpret_cast<float2*>(&Cg[(size_t)m_lo * ldc + nglob]) =
                    make_float2(v00, v01);
                *reinterpret_cast<float2*>(&Cg[(size_t)m_hi * ldc + nglob]) =
                    make_float2(v10, v11);
            } else if (MODE == 1 || !is_v) {
                __half* Cg = C16 + (long long)bz * sC;
                *reinterpret_cast<__half2*>(&Cg[(size_t)m_lo * ldc + nglob]) =
                    __floats2half2_rn(v00, v01);
                *reinterpret_cast<__half2*>(&Cg[(size_t)m_hi * ldc + nglob]) =
                    __floats2half2_rn(v10, v11);
            } else {
                // V region: write V^T [b][d][s]
                const int d = nglob - 2048;
                const int b_lo = m_lo >> 12, s_lo = m_lo & 4095;
                const int b_hi = m_hi >> 12, s_hi = m_hi & 4095;
                VT[((size_t)b_lo * DHEAD + d)     * SEQ + s_lo] = __float2half_rn(v00);
                VT[((size_t)b_lo * DHEAD + d + 1) * SEQ + s_lo] = __float2half_rn(v01);
                VT[((size_t)b_hi * DHEAD + d)     * SEQ + s_hi] = __float2half_rn(v10);
                VT[((size_t)b_hi * DHEAD + d + 1) * SEQ + s_hi] = __float2half_rn(v11);
            }
        }
    }
}

// fp32 -> fp16 elementwise (float4 -> 2x half2), grid-stride
__global__ __launch_bounds__(256) void f2h_kernel(
    const float4* __restrict__ in, uint2* __restrict__ out, size_t n4)
{
    for (size_t i = (size_t)blockIdx.x * blockDim.x + threadIdx.x; i < n4;
         i += (size_t)gridDim.x * blockDim.x) {
        float4 v = in[i];
        uint2 o;
        o.x = h2_bits(__floats2half2_rn(v.x, v.y));
        o.y = h2_bits(__floats2half2_rn(v.z, v.w));
        out[i] = o;
    }
}

// out_h[c][r] = half(in[r][c]); R, C multiples of 32
__global__ __launch_bounds__(256) void transpose_f2h(
    const float* __restrict__ in, __half* __restrict__ out, int R, int C)
{
    __shared__ float t[32][33];
    const int c = blockIdx.x * 32 + threadIdx.x;
    const int r0 = blockIdx.y * 32;
    for (int i = threadIdx.y; i < 32; i += 8)
        t[i][threadIdx.x] = in[(size_t)(r0 + i) * C + c];
    __syncthreads();
    const int rr = r0 + threadIdx.x;
    const int cc = blockIdx.x * 32;
    for (int i = threadIdx.y; i < 32; i += 8)
        out[(size_t)(cc + i) * R + rr] = __float2half_rn(t[threadIdx.x][i]);
}

// Row softmax over 4096 cols: read fp32 scores, write fp16 P. One block per row.
__global__ __launch_bounds__(256) void softmax_h(
    const float* __restrict__ P, __half* __restrict__ Ph)
{
    const size_t row = blockIdx.x;
    const float2* p2 = reinterpret_cast<const float2*>(P + row * (size_t)SEQ);
    __half2* o2 = reinterpret_cast<__half2*>(Ph + row * (size_t)SEQ);
    const int tid = threadIdx.x;

    float2 v[8];
    float mx = -1e30f;
    #pragma unroll
    for (int i = 0; i < 8; i++) {
        v[i] = p2[i * 256 + tid];
        mx = fmaxf(mx, fmaxf(v[i].x, v[i].y));
    }

    __shared__ float red[8];
    #pragma unroll
    for (int off = 16; off; off >>= 1)
        mx = fmaxf(mx, __shfl_xor_sync(0xFFFFFFFFu, mx, off));
    if ((tid & 31) == 0) red[tid >> 5] = mx;
    __syncthreads();
    mx = red[0];
    #pragma unroll
    for (int w = 1; w < 8; w++) mx = fmaxf(mx, red[w]);

    float sum = 0.f;
    #pragma unroll
    for (int i = 0; i < 8; i++) {
        v[i].x = __expf(v[i].x - mx);
        v[i].y = __expf(v[i].y - mx);
        sum += v[i].x + v[i].y;
    }
    __syncthreads();
    #pragma unroll
    for (int off = 16; off; off >>= 1)
        sum += __shfl_xor_sync(0xFFFFFFFFu, sum, off);
    if ((tid & 31) == 0) red[tid >> 5] = sum;
    __syncthreads();
    sum = 0.f;
    #pragma unroll
    for (int w = 0; w < 8; w++) sum += red[w];

    const float inv = 1.f / sum;
    #pragma unroll
    for (int i = 0; i < 8; i++)
        o2[i * 256 + tid] = __floats2half2_rn(v[i].x * inv, v[i].y * inv);
}

extern "C" void kernel_launch(void* const* d_in, const int* in_sizes, int n_in,
                              void* d_out, int out_size)
{
    const float* x    = (const float*)d_in[0];
    const float* Wqkv = (const float*)d_in[1];
    const float* bqkv = (const float*)d_in[2];
    const float* Wo   = (const float*)d_in[3];
    const float* bo   = (const float*)d_in[4];
    float* out = (float*)d_out;

    __half *xh, *wqkvT, *woT, *qkvh, *vth, *attnh, *aouth;
    float *attn;
    cudaGetSymbolAddress((void**)&xh,    g_xh);
    cudaGetSymbolAddress((void**)&wqkvT, g_wqkvT);
    cudaGetSymbolAddress((void**)&woT,   g_woT);
    cudaGetSymbolAddress((void**)&qkvh,  g_qkvh);
    cudaGetSymbolAddress((void**)&vth,   g_vth);
    cudaGetSymbolAddress((void**)&attn,  g_attn);
    cudaGetSymbolAddress((void**)&attnh, g_attnh);
    cudaGetSymbolAddress((void**)&aouth, g_aouth);

    const int SMEM_DYN = NSTAGE * STAGE_BYTES;   // 98304 B
    cudaFuncSetAttribute(hgemm<0>, cudaFuncAttributeMaxDynamicSharedMemorySize, SMEM_DYN);
    cudaFuncSetAttribute(hgemm<1>, cudaFuncAttributeMaxDynamicSharedMemorySize, SMEM_DYN);
    cudaFuncSetAttribute(hgemm<2>, cudaFuncAttributeMaxDynamicSharedMemorySize, SMEM_DYN);

    const int BS = BATCH * SEQ;                      // 16384
    const long long sQKV = (long long)SEQ * 3 * DHEAD;
    const long long sATT = (long long)SEQ * SEQ;
    const long long sVT  = (long long)DHEAD * SEQ;
    const long long sOUT = (long long)SEQ * DHEAD;
    const float scale = 0.03125f;                    // 1/sqrt(1024)
    dim3 blk(256);

    // 0. fp16 conversions: x (elementwise), Wqkv^T and Wo^T (transpose)
    f2h_kernel<<<2048, 256>>>((const float4*)x, (uint2*)xh,
                              (size_t)BS * HID / 4);
    transpose_f2h<<<dim3(3 * DHEAD / 32, HID / 32), dim3(32, 8)>>>(Wqkv, wqkvT, HID, 3 * DHEAD);
    transpose_f2h<<<dim3(HID / 32, DHEAD / 32), dim3(32, 8)>>>(Wo, woT, DHEAD, HID);

    // 1. qkv = x @ Wqkv + bqkv  [16384 x 3072, K=4096]; q,k -> qkvh, v -> vth^T
    hgemm<2><<<dim3(3 * DHEAD / BN, BS / BM, 1), blk, SMEM_DYN>>>(
        xh, HID, 0, wqkvT, HID, 0, bqkv,
        nullptr, qkvh, vth, 3 * DHEAD, 0, HID, 1.f);

    // 2. scores = scale * Q @ K^T  (batched, K=1024) -> fp32 attn
    hgemm<0><<<dim3(SEQ / BN, SEQ / BM, BATCH), blk, SMEM_DYN>>>(
        qkvh, 3 * DHEAD, sQKV, qkvh + DHEAD, 3 * DHEAD, sQKV, nullptr,
        attn, nullptr, nullptr, SEQ, sATT, DHEAD, scale);

    // 3. softmax rows -> fp16 P
    softmax_h<<<BS, 256>>>(attn, attnh);

    // 4. out = P @ V  (batched, K=4096; B = V^T [1024][4096]) -> fp16 aout
    hgemm<1><<<dim3(DHEAD / BN, SEQ / BM, BATCH), blk, SMEM_DYN>>>(
        attnh, SEQ, sATT, vth, SEQ, sVT, nullptr,
        nullptr, aouth, nullptr, DHEAD, sOUT, SEQ, 1.f);

    // 5. y = out @ Wo + bo  [16384 x 4096, K=1024] -> fp32
    hgemm<0><<<dim3(HID / BN, BS / BM, 1), blk, SMEM_DYN>>>(
        aouth, DHEAD, 0, woT, DHEAD, 0, bo,
        out, nullptr, nullptr, HID, 0, DHEAD, 1.f);
}